// round 15
// baseline (speedup 1.0000x reference)
#include <cuda_runtime.h>
#include <cuda_bf16.h>
#include <cstdint>

// Problem constants
#define BATCH 2
#define S_LEN 2048
#define EMB   1024
#define NH    16
#define HD    64
#define QKV_N (3 * EMB)        // 3072
#define ROWS  (BATCH * S_LEN)  // 4096
#define GK    EMB              // GEMM K = 1024 for both GEMMs

// ---------------------------------------------------------------------------
// Scratch (device globals — allocation-free)
// ---------------------------------------------------------------------------
__device__ __align__(256) __nv_bfloat16 g_qkvh[ (size_t)ROWS * QKV_N ]; // QKV hi (flash input)
__device__ __align__(256) __nv_bfloat16 g_qkvl[ (size_t)ROWS * QKV_N ]; // QKV lo
__device__ __align__(256) float g_attn[ (size_t)ROWS * EMB ];           // flash out fp32
// int8 quantized operands (hi = q1, residual = q2, value = s*(q1 + q2/64))
__device__ __align__(256) int8_t g_x1 [ (size_t)ROWS * EMB ];
__device__ __align__(256) int8_t g_x2 [ (size_t)ROWS * EMB ];
__device__ __align__(256) int8_t g_at1[ (size_t)ROWS * EMB ];
__device__ __align__(256) int8_t g_at2[ (size_t)ROWS * EMB ];
__device__ __align__(256) int8_t g_wq1[ (size_t)QKV_N * EMB ];  // [N,K]
__device__ __align__(256) int8_t g_wq2[ (size_t)QKV_N * EMB ];
__device__ __align__(256) int8_t g_wp1[ (size_t)EMB * EMB ];
__device__ __align__(256) int8_t g_wp2[ (size_t)EMB * EMB ];
// scales + max-bits scratch
__device__ float g_sx [ROWS];
__device__ float g_sat[ROWS];
__device__ float g_swq[QKV_N];
__device__ float g_swp[EMB];
__device__ unsigned int g_mq[QKV_N];
__device__ unsigned int g_mp[EMB];

// ---------------------------------------------------------------------------
// helpers (non-arch-gated PTX only: cp.async / ldmatrix / mma.sync)
// ---------------------------------------------------------------------------
__device__ __forceinline__ uint32_t smem_u32(const void* p) {
    uint32_t a;
    asm("{ .reg .u64 t; cvta.to.shared.u64 t, %1; cvt.u32.u64 %0, t; }"
        : "=r"(a) : "l"(p));
    return a;
}

#define CP_ASYNC16(dst, src) \
    asm volatile("cp.async.cg.shared.global [%0], [%1], 16;" :: "r"(dst), "l"(src))
#define CP_COMMIT() asm volatile("cp.async.commit_group;" ::: "memory")
#define CP_WAIT(n)  asm volatile("cp.async.wait_group %0;" :: "n"(n) : "memory")

#define LDMATRIX_X4(r0, r1, r2, r3, addr) \
    asm volatile("ldmatrix.sync.aligned.m8n8.x4.shared.b16 {%0,%1,%2,%3}, [%4];" \
                 : "=r"(r0), "=r"(r1), "=r"(r2), "=r"(r3) : "r"(addr))

#define LDMATRIX_X4_T(r0, r1, r2, r3, addr) \
    asm volatile("ldmatrix.sync.aligned.m8n8.x4.trans.shared.b16 {%0,%1,%2,%3}, [%4];" \
                 : "=r"(r0), "=r"(r1), "=r"(r2), "=r"(r3) : "r"(addr))

#define MMA16816(c0, c1, c2, c3, a0, a1, a2, a3, b0, b1)                        \
    asm volatile("mma.sync.aligned.m16n8k16.row.col.f32.bf16.bf16.f32 "         \
                 "{%0,%1,%2,%3}, {%4,%5,%6,%7}, {%8,%9}, {%0,%1,%2,%3};"        \
                 : "+f"(c0), "+f"(c1), "+f"(c2), "+f"(c3)                       \
                 : "r"(a0), "r"(a1), "r"(a2), "r"(a3), "r"(b0), "r"(b1))

#define IMMA16832(c0, c1, c2, c3, a0, a1, a2, a3, b0, b1)                       \
    asm volatile("mma.sync.aligned.m16n8k32.row.col.s32.s8.s8.s32 "             \
                 "{%0,%1,%2,%3}, {%4,%5,%6,%7}, {%8,%9}, {%0,%1,%2,%3};"        \
                 : "+r"(c0), "+r"(c1), "+r"(c2), "+r"(c3)                       \
                 : "r"(a0), "r"(a1), "r"(a2), "r"(a3), "r"(b0), "r"(b1))

__device__ __forceinline__ uint32_t bf2u(__nv_bfloat162 v) {
    return *reinterpret_cast<uint32_t*>(&v);
}

// ---------------------------------------------------------------------------
// Row quantization: per-row scale s = max|row|/127; q1 = rint(v/s) in [-127,127],
// q2 = rint((v/s - q1)*64) in [-32,32]. K = 1024 fixed (one float4 per thread).
// ---------------------------------------------------------------------------
__global__ void rowquant_kernel(const float* __restrict__ in,
                                char4* __restrict__ q1,
                                char4* __restrict__ q2,
                                float* __restrict__ srow)
{
    __shared__ float red[256];
    const int row = blockIdx.x;
    const int tid = threadIdx.x;
    float4 v = ((const float4*)in)[(size_t)row * 256 + tid];
    float m = fmaxf(fmaxf(fabsf(v.x), fabsf(v.y)), fmaxf(fabsf(v.z), fabsf(v.w)));
    red[tid] = m;
    __syncthreads();
    for (int s = 128; s > 0; s >>= 1) {
        if (tid < s) red[tid] = fmaxf(red[tid], red[tid + s]);
        __syncthreads();
    }
    const float mx  = fmaxf(red[0], 1e-20f);
    const float s   = mx / 127.f;
    const float inv = 127.f / mx;
    if (tid == 0) srow[row] = s;

    float q[4] = { v.x * inv, v.y * inv, v.z * inv, v.w * inv };
    char a1[4], a2[4];
#pragma unroll
    for (int i = 0; i < 4; i++) {
        int i1 = __float2int_rn(q[i]);
        int i2 = __float2int_rn((q[i] - (float)i1) * 64.f);
        a1[i] = (char)i1;
        a2[i] = (char)i2;
    }
    char4 c1; c1.x = a1[0]; c1.y = a1[1]; c1.z = a1[2]; c1.w = a1[3];
    char4 c2; c2.x = a2[0]; c2.y = a2[1]; c2.z = a2[2]; c2.w = a2[3];
    q1[(size_t)row * 256 + tid] = c1;
    q2[(size_t)row * 256 + tid] = c2;
}

// ---------------------------------------------------------------------------
// Weight column-max (abs), via atomicMax on float bits (non-negative floats)
// ---------------------------------------------------------------------------
__global__ void zero_kernel(unsigned int* p, int n)
{
    int i = blockIdx.x * blockDim.x + threadIdx.x;
    if (i < n) p[i] = 0u;
}

__global__ void colmax_kernel(const float* __restrict__ W,
                              unsigned int* __restrict__ mbits, int K, int N)
{
    const int n  = blockIdx.x * 256 + threadIdx.x;
    const int k0 = blockIdx.y * (K / 16);
    float m = 0.f;
    for (int k = k0; k < k0 + K / 16; k++)
        m = fmaxf(m, fabsf(W[(size_t)k * N + n]));
    atomicMax(&mbits[n], __float_as_uint(m));
}

__global__ void scalek_kernel(const unsigned int* __restrict__ mbits,
                              float* __restrict__ s, int n)
{
    int i = blockIdx.x * blockDim.x + threadIdx.x;
    if (i < n) s[i] = fmaxf(__uint_as_float(mbits[i]), 1e-20f) / 127.f;
}

// Transpose + quantize: W[K,N] fp32 -> B1,B2 [N,K] int8
__global__ void wquant_kernel(const float* __restrict__ W,
                              const unsigned int* __restrict__ mbits,
                              int8_t* __restrict__ B1,
                              int8_t* __restrict__ B2, int K, int N)
{
    __shared__ float t[32][33];
    int tx = threadIdx.x, ty = threadIdx.y;
    int n0 = blockIdx.x * 32, k0 = blockIdx.y * 32;
    for (int j = ty; j < 32; j += 8)
        t[j][tx] = W[(size_t)(k0 + j) * N + n0 + tx];
    __syncthreads();
    for (int j = ty; j < 32; j += 8) {
        int n = n0 + j;
        float inv = 127.f / fmaxf(__uint_as_float(mbits[n]), 1e-20f);
        float q = t[tx][j] * inv;   // = W[k0+tx][n] scaled
        int i1 = __float2int_rn(q);
        int i2 = __float2int_rn((q - (float)i1) * 64.f);
        size_t o = (size_t)n * K + k0 + tx;
        B1[o] = (int8_t)i1;
        B2[o] = (int8_t)i2;
    }
}

// ---------------------------------------------------------------------------
// int8 hi/lo GEMM via mma.sync m16n8k32.s8 (3 IMMA terms, exact s32 acc):
// C = sA[row]*sB[col]*(S11 + (S12+S21)/64) + bias.
// CTA 128x128, BKI=64 int8 (64B rows — identical addressing/swizzle to bf16 BK=32),
// 3-stage cp.async pipeline, 16 K-stages.
// Epilogue: Ch!=null -> bf16 hi/lo split; else fp32.
// ---------------------------------------------------------------------------
#define BKI 64
#define NSTAGE_I (GK / BKI)   // 16
#define STG_BYTES 32768
#define NPIPE 3

__global__ __launch_bounds__(256, 1)
void gemm_imma_kernel(const int8_t* __restrict__ A1,
                      const int8_t* __restrict__ A2,
                      const int8_t* __restrict__ B1,
                      const int8_t* __restrict__ B2,
                      const float* __restrict__ sA,
                      const float* __restrict__ sB,
                      const float* __restrict__ bias,
                      float* __restrict__ C,
                      __nv_bfloat16* __restrict__ Ch,
                      __nv_bfloat16* __restrict__ Cl, int N)
{
    extern __shared__ char smc[];
    const uint32_t sbase = smem_u32(smc);
    const int tid  = threadIdx.x;
    const int wid  = tid >> 5;
    const int lane = tid & 31;
    const int bn = blockIdx.x, bm = blockIdx.y;
    const int wm = wid >> 1;
    const int wn = wid & 1;

    const int8_t* gT[4] = {
        A1 + (size_t)bm * 128 * GK, A2 + (size_t)bm * 128 * GK,
        B1 + (size_t)bn * 128 * GK, B2 + (size_t)bn * 128 * GK };

    auto stage_load = [&](int c) {
        const int s  = c % NPIPE;
        const int k0 = c * BKI;
#pragma unroll
        for (int t = 0; t < 4; t++) {
            const int8_t* g = gT[t];
            const uint32_t sb = sbase + s * STG_BYTES + t * 8192;
#pragma unroll
            for (int r2 = 0; r2 < 2; r2++) {
                int idx = tid + r2 * 256;
                int row = idx >> 2;
                int ch  = idx & 3;
                int sw  = ch ^ ((row >> 1) & 3);
                const int8_t* src = g + (size_t)row * GK + k0 + ch * 16;
                CP_ASYNC16(sb + row * 64 + sw * 16, src);
            }
        }
        CP_COMMIT();
    };

    int acc11[2][8][4];
    int accX [2][8][4];
#pragma unroll
    for (int i = 0; i < 2; i++)
#pragma unroll
        for (int j = 0; j < 8; j++)
#pragma unroll
            for (int q = 0; q < 4; q++) { acc11[i][j][q] = 0; accX[i][j][q] = 0; }

    stage_load(0);
    stage_load(1);
    CP_WAIT(1);
    __syncthreads();

    for (int c = 0; c < NSTAGE_I; c++) {
        if (c + 2 < NSTAGE_I) stage_load(c + 2);

        const uint32_t st = sbase + (uint32_t)(c % NPIPE) * STG_BYTES;
        const uint32_t sAq[2] = { st, st + 8192 };
        const uint32_t sBq[2] = { st + 16384, st + 24576 };

#pragma unroll
        for (int kk = 0; kk < 2; kk++) {   // two k32 halves of BKI=64
            uint32_t a[2][2][4];
#pragma unroll
            for (int hl = 0; hl < 2; hl++)
#pragma unroll
                for (int mf = 0; mf < 2; mf++) {
                    int row = wm * 32 + mf * 16 + (lane & 7) + ((lane >> 3) & 1) * 8;
                    int ch  = kk * 2 + (lane >> 4);
                    int sw  = ch ^ ((row >> 1) & 3);
                    uint32_t addr = sAq[hl] + row * 64 + sw * 16;
                    LDMATRIX_X4(a[hl][mf][0], a[hl][mf][1], a[hl][mf][2], a[hl][mf][3], addr);
                }
            uint32_t b[2][4][4];
#pragma unroll
            for (int hl = 0; hl < 2; hl++)
#pragma unroll
                for (int p = 0; p < 4; p++) {
                    int row = wn * 64 + p * 16 + (lane & 7) + (lane >> 4) * 8;
                    int ch  = kk * 2 + ((lane >> 3) & 1);
                    int sw  = ch ^ ((row >> 1) & 3);
                    uint32_t addr = sBq[hl] + row * 64 + sw * 16;
                    LDMATRIX_X4(b[hl][p][0], b[hl][p][1], b[hl][p][2], b[hl][p][3], addr);
                }
            // pass 0: S11 += A1*B1 ; pass 1: SX += A1*B2 ; pass 2: SX += A2*B1
#pragma unroll
            for (int pass = 0; pass < 3; pass++) {
                const int ahl = (pass == 2) ? 1 : 0;
                const int bhl = (pass == 1) ? 1 : 0;
#pragma unroll
                for (int mf = 0; mf < 2; mf++)
#pragma unroll
                    for (int p = 0; p < 4; p++)
#pragma unroll
                        for (int h = 0; h < 2; h++) {
                            int* cc = (pass == 0) ? acc11[mf][p * 2 + h]
                                                  : accX [mf][p * 2 + h];
                            IMMA16832(cc[0], cc[1], cc[2], cc[3],
                                      a[ahl][mf][0], a[ahl][mf][1],
                                      a[ahl][mf][2], a[ahl][mf][3],
                                      b[bhl][p][h * 2], b[bhl][p][h * 2 + 1]);
                        }
            }
        }

        if (c + 2 < NSTAGE_I)      CP_WAIT(1);
        else if (c + 1 < NSTAGE_I) CP_WAIT(0);
        __syncthreads();
    }

    const int g = lane >> 2, t2 = (lane & 3) * 2;
    const float QINV = 1.f / 64.f;
#pragma unroll
    for (int mf = 0; mf < 2; mf++) {
        int row0 = bm * 128 + wm * 32 + mf * 16 + g;
        float sr0 = sA[row0], sr1 = sA[row0 + 8];
#pragma unroll
        for (int nf = 0; nf < 8; nf++) {
            int col = bn * 128 + wn * 64 + nf * 8 + t2;
            float sc0 = sB[col], sc1 = sB[col + 1];
            float bx = bias[col], by = bias[col + 1];
            float v0 = sr0 * sc0 * ((float)acc11[mf][nf][0] + (float)accX[mf][nf][0] * QINV) + bx;
            float v1 = sr0 * sc1 * ((float)acc11[mf][nf][1] + (float)accX[mf][nf][1] * QINV) + by;
            float v2 = sr1 * sc0 * ((float)acc11[mf][nf][2] + (float)accX[mf][nf][2] * QINV) + bx;
            float v3 = sr1 * sc1 * ((float)acc11[mf][nf][3] + (float)accX[mf][nf][3] * QINV) + by;
            if (Ch) {
                __nv_bfloat162 h01 = __floats2bfloat162_rn(v0, v1);
                __nv_bfloat162 h23 = __floats2bfloat162_rn(v2, v3);
                __nv_bfloat162 l01 = __floats2bfloat162_rn(
                    v0 - __bfloat162float(h01.x), v1 - __bfloat162float(h01.y));
                __nv_bfloat162 l23 = __floats2bfloat162_rn(
                    v2 - __bfloat162float(h23.x), v3 - __bfloat162float(h23.y));
                *(__nv_bfloat162*)(Ch + (size_t)row0 * N + col)       = h01;
                *(__nv_bfloat162*)(Cl + (size_t)row0 * N + col)       = l01;
                *(__nv_bfloat162*)(Ch + (size_t)(row0 + 8) * N + col) = h23;
                *(__nv_bfloat162*)(Cl + (size_t)(row0 + 8) * N + col) = l23;
            } else {
                float2 f0; f0.x = v0; f0.y = v1;
                float2 f1; f1.x = v2; f1.y = v3;
                *(float2*)(C + (size_t)row0 * N + col)       = f0;
                *(float2*)(C + (size_t)(row0 + 8) * N + col) = f1;
            }
        }
    }
}

// ---------------------------------------------------------------------------
// Tensor-core flash attention (bf16 hi/lo compensated, causal). Unchanged core;
// epilogue now writes fp32 attn (re-quantized afterwards for the proj GEMM).
// ---------------------------------------------------------------------------
__global__ __launch_bounds__(256, 2)
void flash_mma_kernel(const __nv_bfloat16* __restrict__ qkvh,
                      const __nv_bfloat16* __restrict__ qkvl,
                      float* __restrict__ attn)
{
    extern __shared__ char smf[];
    const uint32_t sb = smem_u32(smf);
    const int tid = threadIdx.x, wid = tid >> 5, lane = tid & 31;
    const int qt = (int)gridDim.x - 1 - (int)blockIdx.x;  // heavy tiles first
    const int h = blockIdx.y, b = blockIdx.z;
    const int g = lane >> 2, t = lane & 3;

    const size_t rowbase = (size_t)b * S_LEN * QKV_N + (size_t)h * HD;

    for (int i = tid; i < 2048; i += 256) {
        int arr = i >> 10;
        int r   = (i >> 3) & 127;
        int ch  = i & 7;
        const __nv_bfloat16* src =
            (arr ? qkvl : qkvh) + rowbase + (size_t)(qt * 128 + r) * QKV_N + ch * 8;
        CP_ASYNC16(sb + arr * 16384 + r * 128 + ((ch ^ (r & 7)) << 4), src);
    }

    auto stage_kv = [&](int kt) {
        const int s = kt & 1;
        for (int i = tid; i < 2048; i += 256) {
            int sub = i >> 9;            // 0 Kh, 1 Kl, 2 Vh, 3 Vl
            int r   = (i >> 3) & 63;
            int ch  = i & 7;
            size_t go = rowbase + (size_t)(kt * 64 + r) * QKV_N + ch * 8
                      + ((sub >> 1) ? 2 * (size_t)EMB : (size_t)EMB);
            const __nv_bfloat16* gp = (sub & 1) ? qkvl + go : qkvh + go;
            CP_ASYNC16(sb + 32768 + s * 32768 + sub * 8192 + r * 128
                       + ((ch ^ (r & 7)) << 4), gp);
        }
        CP_COMMIT();
    };

    stage_kv(0);

    float m_[2] = { -1e30f, -1e30f }, l_[2] = { 0.f, 0.f };
    float oacc[8][4];
#pragma unroll
    for (int i = 0; i < 8; i++)
#pragma unroll
        for (int j = 0; j < 4; j++) oacc[i][j] = 0.f;

    const int nkt  = 2 * qt + 2;
    const int wrow = qt * 128 + wid * 16;

    for (int kt = 0; kt < nkt; kt++) {
        if (kt + 1 < nkt) { stage_kv(kt + 1); CP_WAIT(1); }
        else              { CP_WAIT(0); }
        __syncthreads();

        const bool active = (kt * 64) <= (wrow + 15);
        if (active) {
            const uint32_t stK = sb + 32768 + (uint32_t)(kt & 1) * 32768;
            const uint32_t stV = stK + 16384;

            float sacc[8][4];
#pragma unroll
            for (int i = 0; i < 8; i++)
#pragma unroll
                for (int j = 0; j < 4; j++) sacc[i][j] = 0.f;

#pragma unroll
            for (int kk = 0; kk < 4; kk++) {
                uint32_t aH[4], aL[4];
                {
                    int row = wid * 16 + (lane & 7) + ((lane >> 3) & 1) * 8;
                    int ch  = 2 * kk + (lane >> 4);
                    uint32_t ad = sb + row * 128 + ((ch ^ (row & 7)) << 4);
                    LDMATRIX_X4(aH[0], aH[1], aH[2], aH[3], ad);
                    LDMATRIX_X4(aL[0], aL[1], aL[2], aL[3], ad + 16384);
                }
#pragma unroll
                for (int p = 0; p < 4; p++) {
                    uint32_t bH[4], bL[4];
                    int row = p * 16 + (lane & 7) + (lane >> 4) * 8;
                    int ch  = 2 * kk + ((lane >> 3) & 1);
                    uint32_t bd = stK + row * 128 + ((ch ^ (row & 7)) << 4);
                    LDMATRIX_X4(bH[0], bH[1], bH[2], bH[3], bd);
                    LDMATRIX_X4(bL[0], bL[1], bL[2], bL[3], bd + 8192);
#pragma unroll
                    for (int term = 0; term < 3; term++) {
                        const uint32_t* aa = (term == 2) ? aL : aH;
                        const uint32_t* bb = (term == 1) ? bL : bH;
#pragma unroll
                        for (int hh = 0; hh < 2; hh++) {
                            float* cc = sacc[2 * p + hh];
                            MMA16816(cc[0], cc[1], cc[2], cc[3],
                                     aa[0], aa[1], aa[2], aa[3],
                                     bb[2 * hh], bb[2 * hh + 1]);
                        }
                    }
                }
            }

            const int r0g = wrow + g;
#pragma unroll
            for (int nf = 0; nf < 8; nf++) {
                int c0 = kt * 64 + nf * 8 + 2 * t;
#pragma unroll
                for (int e = 0; e < 2; e++) {
                    int col = c0 + e;
                    sacc[nf][e]     = (col <= r0g)     ? sacc[nf][e] * 0.125f     : -1e30f;
                    sacc[nf][2 + e] = (col <= r0g + 8) ? sacc[nf][2 + e] * 0.125f : -1e30f;
                }
            }

#pragma unroll
            for (int hf = 0; hf < 2; hf++) {
                float mx = -1e30f;
#pragma unroll
                for (int nf = 0; nf < 8; nf++)
                    mx = fmaxf(mx, fmaxf(sacc[nf][2 * hf], sacc[nf][2 * hf + 1]));
                mx = fmaxf(mx, __shfl_xor_sync(0xffffffffu, mx, 1));
                mx = fmaxf(mx, __shfl_xor_sync(0xffffffffu, mx, 2));
                float mnew  = fmaxf(m_[hf], mx);
                float alpha = __expf(m_[hf] - mnew);
                float rsum = 0.f;
#pragma unroll
                for (int nf = 0; nf < 8; nf++) {
                    float e0 = __expf(sacc[nf][2 * hf] - mnew);
                    float e1 = __expf(sacc[nf][2 * hf + 1] - mnew);
                    sacc[nf][2 * hf] = e0; sacc[nf][2 * hf + 1] = e1;
                    rsum += e0 + e1;
                }
                rsum += __shfl_xor_sync(0xffffffffu, rsum, 1);
                rsum += __shfl_xor_sync(0xffffffffu, rsum, 2);
                l_[hf] = l_[hf] * alpha + rsum;
                m_[hf] = mnew;
#pragma unroll
                for (int nf = 0; nf < 8; nf++) {
                    oacc[nf][2 * hf]     *= alpha;
                    oacc[nf][2 * hf + 1] *= alpha;
                }
            }

#pragma unroll
            for (int s16 = 0; s16 < 4; s16++) {
                uint32_t pH[4], pL[4];
                {
                    const int nfl = 2 * s16, nfh = 2 * s16 + 1;
                    __nv_bfloat162 h0 = __floats2bfloat162_rn(sacc[nfl][0], sacc[nfl][1]);
                    __nv_bfloat162 h1 = __floats2bfloat162_rn(sacc[nfl][2], sacc[nfl][3]);
                    __nv_bfloat162 h2 = __floats2bfloat162_rn(sacc[nfh][0], sacc[nfh][1]);
                    __nv_bfloat162 h3 = __floats2bfloat162_rn(sacc[nfh][2], sacc[nfh][3]);
                    pH[0] = bf2u(h0); pH[1] = bf2u(h1); pH[2] = bf2u(h2); pH[3] = bf2u(h3);
                    __nv_bfloat162 e0 = __floats2bfloat162_rn(
                        sacc[nfl][0] - __bfloat162float(h0.x), sacc[nfl][1] - __bfloat162float(h0.y));
                    __nv_bfloat162 e1 = __floats2bfloat162_rn(
                        sacc[nfl][2] - __bfloat162float(h1.x), sacc[nfl][3] - __bfloat162float(h1.y));
                    __nv_bfloat162 e2 = __floats2bfloat162_rn(
                        sacc[nfh][0] - __bfloat162float(h2.x), sacc[nfh][1] - __bfloat162float(h2.y));
                    __nv_bfloat162 e3 = __floats2bfloat162_rn(
                        sacc[nfh][2] - __bfloat162float(h3.x), sacc[nfh][3] - __bfloat162float(h3.y));
                    pL[0] = bf2u(e0); pL[1] = bf2u(e1); pL[2] = bf2u(e2); pL[3] = bf2u(e3);
                }
#pragma unroll
                for (int p = 0; p < 4; p++) {
                    uint32_t vH[4], vL[4];
                    int row = s16 * 16 + (lane & 7) + ((lane >> 3) & 1) * 8;
                    int ch  = 2 * p + (lane >> 4);
                    uint32_t vd = stV + row * 128 + ((ch ^ (row & 7)) << 4);
                    LDMATRIX_X4_T(vH[0], vH[1], vH[2], vH[3], vd);
                    LDMATRIX_X4_T(vL[0], vL[1], vL[2], vL[3], vd + 8192);
#pragma unroll
                    for (int term = 0; term < 3; term++) {
                        const uint32_t* pp = (term == 2) ? pL : pH;
                        const uint32_t* vv = (term == 1) ? vL : vH;
#pragma unroll
                        for (int hh = 0; hh < 2; hh++) {
                            float* cc = oacc[2 * p + hh];
                            MMA16816(cc[0], cc[1], cc[2], cc[3],
                                     pp[0], pp[1], pp[2], pp[3],
                                     vv[2 * hh], vv[2 * hh + 1]);
                        }
                    }
                }
            }
        }
        __syncthreads();
    }

    // epilogue: O / l -> fp32
    const float inv0 = 1.f / l_[0], inv1 = 1.f / l_[1];
    const int grow0 = qt * 128 + wid * 16 + g;
    const size_t obase = (size_t)b * S_LEN * EMB + (size_t)h * HD;
#pragma unroll
    for (int nf = 0; nf < 8; nf++) {
        int d = nf * 8 + 2 * t;
        float2 f0; f0.x = oacc[nf][0] * inv0; f0.y = oacc[nf][1] * inv0;
        float2 f1; f1.x = oacc[nf][2] * inv1; f1.y = oacc[nf][3] * inv1;
        *(float2*)(attn + obase + (size_t)grow0 * EMB + d)       = f0;
        *(float2*)(attn + obase + (size_t)(grow0 + 8) * EMB + d) = f1;
    }
}

// ---------------------------------------------------------------------------
// launch
// ---------------------------------------------------------------------------
extern "C" void kernel_launch(void* const* d_in, const int* in_sizes, int n_in,
                              void* d_out, int out_size)
{
    const float* x     = (const float*)d_in[0];
    const float* wqkv  = (const float*)d_in[1];
    const float* bqkv  = (const float*)d_in[2];
    const float* wproj = (const float*)d_in[3];
    const float* bproj = (const float*)d_in[4];
    float* out = (float*)d_out;

    __nv_bfloat16 *qkvh, *qkvl;
    float *attn, *sx, *sat, *swq, *swp;
    int8_t *x1, *x2, *at1, *at2, *wq1, *wq2, *wp1, *wp2;
    unsigned int *mq, *mp;
    cudaGetSymbolAddress((void**)&qkvh, g_qkvh);
    cudaGetSymbolAddress((void**)&qkvl, g_qkvl);
    cudaGetSymbolAddress((void**)&attn, g_attn);
    cudaGetSymbolAddress((void**)&x1,   g_x1);
    cudaGetSymbolAddress((void**)&x2,   g_x2);
    cudaGetSymbolAddress((void**)&at1,  g_at1);
    cudaGetSymbolAddress((void**)&at2,  g_at2);
    cudaGetSymbolAddress((void**)&wq1,  g_wq1);
    cudaGetSymbolAddress((void**)&wq2,  g_wq2);
    cudaGetSymbolAddress((void**)&wp1,  g_wp1);
    cudaGetSymbolAddress((void**)&wp2,  g_wp2);
    cudaGetSymbolAddress((void**)&sx,   g_sx);
    cudaGetSymbolAddress((void**)&sat,  g_sat);
    cudaGetSymbolAddress((void**)&swq,  g_swq);
    cudaGetSymbolAddress((void**)&swp,  g_swp);
    cudaGetSymbolAddress((void**)&mq,   g_mq);
    cudaGetSymbolAddress((void**)&mp,   g_mp);

    const int gemm_smem  = NPIPE * STG_BYTES;       // 96 KB
    const int flash_smem = 32768 + 2 * 32768;       // 96 KB
    cudaFuncSetAttribute(gemm_imma_kernel,
                         cudaFuncAttributeMaxDynamicSharedMemorySize, gemm_smem);
    cudaFuncSetAttribute(flash_mma_kernel,
                         cudaFuncAttributeMaxDynamicSharedMemorySize, flash_smem);

    // 0) quantize X and both weight matrices
    rowquant_kernel<<<ROWS, 256>>>(x, (char4*)x1, (char4*)x2, sx);
    zero_kernel<<<(QKV_N + 255) / 256, 256>>>(mq, QKV_N);
    zero_kernel<<<(EMB + 255) / 256, 256>>>(mp, EMB);
    colmax_kernel<<<dim3(QKV_N / 256, 16), 256>>>(wqkv, mq, EMB, QKV_N);
    colmax_kernel<<<dim3(EMB / 256, 16), 256>>>(wproj, mp, EMB, EMB);
    scalek_kernel<<<(QKV_N + 255) / 256, 256>>>(mq, swq, QKV_N);
    scalek_kernel<<<(EMB + 255) / 256, 256>>>(mp, swp, EMB);
    {
        dim3 wb(32, 8);
        wquant_kernel<<<dim3(QKV_N / 32, EMB / 32), wb>>>(wqkv, mq, wq1, wq2, EMB, QKV_N);
        wquant_kernel<<<dim3(EMB / 32, EMB / 32), wb>>>(wproj, mp, wp1, wp2, EMB, EMB);
    }

    // 1) QKV = X @ Wqkv + b  (int8 IMMA) -> bf16 hi/lo for flash
    {
        dim3 grid(QKV_N / 128, ROWS / 128);
        gemm_imma_kernel<<<grid, 256, gemm_smem>>>(x1, x2, wq1, wq2, sx, swq,
                                                   bqkv, nullptr, qkvh, qkvl, QKV_N);
    }

    // 2) tensor-core causal flash attention -> fp32 attn
    {
        dim3 grid(S_LEN / 128, NH, BATCH);
        flash_mma_kernel<<<grid, 256, flash_smem>>>(qkvh, qkvl, attn);
    }

    // 3) quantize attn rows, then out = attn @ Wproj + b (int8 IMMA, fp32 out)
    rowquant_kernel<<<ROWS, 256>>>(attn, (char4*)at1, (char4*)at2, sat);
    {
        dim3 grid(EMB / 128, ROWS / 128);
        gemm_imma_kernel<<<grid, 256, gemm_smem>>>(at1, at2, wp1, wp2, sat, swp,
                                                   bproj, out, nullptr, nullptr, EMB);
    }
}

// round 16
// speedup vs baseline: 3.1370x; 3.1370x over previous
#include <cuda_runtime.h>
#include <cuda_bf16.h>
#include <cuda_fp16.h>
#include <cstdint>

// Problem constants
#define BATCH 2
#define S_LEN 2048
#define EMB   1024
#define NH    16
#define HD    64
#define QKV_N (3 * EMB)        // 3072
#define ROWS  (BATCH * S_LEN)  // 4096
#define GK    EMB              // GEMM K = 1024 for both GEMMs

// ---------------------------------------------------------------------------
// Scratch (device globals — allocation-free)
// ---------------------------------------------------------------------------
__device__ __align__(256) __nv_bfloat16 g_qkvh[ (size_t)ROWS * QKV_N ]; // QKV hi (flash)
__device__ __align__(256) __nv_bfloat16 g_qkvl[ (size_t)ROWS * QKV_N ]; // QKV lo (flash)
__device__ __align__(256) __half g_x16 [ (size_t)ROWS * EMB ];          // X fp16
__device__ __align__(256) __half g_at16[ (size_t)ROWS * EMB ];          // attn fp16
__device__ __align__(256) __half g_wq16[ (size_t)QKV_N * EMB ];         // Wqkv^T [N,K] fp16
__device__ __align__(256) __half g_wp16[ (size_t)EMB * EMB ];           // Wproj^T [N,K] fp16

// ---------------------------------------------------------------------------
// helpers (non-arch-gated PTX only: cp.async / ldmatrix / mma.sync)
// ---------------------------------------------------------------------------
__device__ __forceinline__ uint32_t smem_u32(const void* p) {
    uint32_t a;
    asm("{ .reg .u64 t; cvta.to.shared.u64 t, %1; cvt.u32.u64 %0, t; }"
        : "=r"(a) : "l"(p));
    return a;
}

#define CP_ASYNC16(dst, src) \
    asm volatile("cp.async.cg.shared.global [%0], [%1], 16;" :: "r"(dst), "l"(src))
#define CP_COMMIT() asm volatile("cp.async.commit_group;" ::: "memory")
#define CP_WAIT(n)  asm volatile("cp.async.wait_group %0;" :: "n"(n) : "memory")

#define LDMATRIX_X4(r0, r1, r2, r3, addr) \
    asm volatile("ldmatrix.sync.aligned.m8n8.x4.shared.b16 {%0,%1,%2,%3}, [%4];" \
                 : "=r"(r0), "=r"(r1), "=r"(r2), "=r"(r3) : "r"(addr))

#define LDMATRIX_X4_T(r0, r1, r2, r3, addr) \
    asm volatile("ldmatrix.sync.aligned.m8n8.x4.trans.shared.b16 {%0,%1,%2,%3}, [%4];" \
                 : "=r"(r0), "=r"(r1), "=r"(r2), "=r"(r3) : "r"(addr))

// bf16 MMA (flash)
#define MMA16816(c0, c1, c2, c3, a0, a1, a2, a3, b0, b1)                        \
    asm volatile("mma.sync.aligned.m16n8k16.row.col.f32.bf16.bf16.f32 "         \
                 "{%0,%1,%2,%3}, {%4,%5,%6,%7}, {%8,%9}, {%0,%1,%2,%3};"        \
                 : "+f"(c0), "+f"(c1), "+f"(c2), "+f"(c3)                       \
                 : "r"(a0), "r"(a1), "r"(a2), "r"(a3), "r"(b0), "r"(b1))

// fp16 MMA (GEMMs)
#define MMA16816H(c0, c1, c2, c3, a0, a1, a2, a3, b0, b1)                       \
    asm volatile("mma.sync.aligned.m16n8k16.row.col.f32.f16.f16.f32 "           \
                 "{%0,%1,%2,%3}, {%4,%5,%6,%7}, {%8,%9}, {%0,%1,%2,%3};"        \
                 : "+f"(c0), "+f"(c1), "+f"(c2), "+f"(c3)                       \
                 : "r"(a0), "r"(a1), "r"(a2), "r"(a3), "r"(b0), "r"(b1))

__device__ __forceinline__ uint32_t bf2u(__nv_bfloat162 v) {
    return *reinterpret_cast<uint32_t*>(&v);
}

// ---------------------------------------------------------------------------
// fp32 -> fp16 convert (float4 vectorized)
// ---------------------------------------------------------------------------
__global__ void conv16_kernel(const float* __restrict__ in,
                              __half* __restrict__ out, int n4)
{
    int i = blockIdx.x * blockDim.x + threadIdx.x;
    if (i >= n4) return;
    float4 v = ((const float4*)in)[i];
    __half2 h0 = __floats2half2_rn(v.x, v.y);
    __half2 h1 = __floats2half2_rn(v.z, v.w);
    ((__half2*)out)[2 * i]     = h0;
    ((__half2*)out)[2 * i + 1] = h1;
}

// ---------------------------------------------------------------------------
// Weight transpose + convert: W[K,N] fp32 -> T[N,K] fp16
// ---------------------------------------------------------------------------
__global__ void wconv_kernel(const float* __restrict__ W,
                             __half* __restrict__ T, int K, int N)
{
    __shared__ float t[32][33];
    int tx = threadIdx.x, ty = threadIdx.y;
    int n0 = blockIdx.x * 32, k0 = blockIdx.y * 32;
    for (int j = ty; j < 32; j += 8)
        t[j][tx] = W[(size_t)(k0 + j) * N + n0 + tx];
    __syncthreads();
    for (int j = ty; j < 32; j += 8)
        T[(size_t)(n0 + j) * K + k0 + tx] = __float2half_rn(t[tx][j]);
}

// ---------------------------------------------------------------------------
// fp16 single-pass GEMM via mma.sync m16n8k16.f16: C = A@Bt^T + bias.
// A: [M,GK] fp16 K-major; Bt: [N,GK] fp16 K-major.
// CTA 128x128, BKH=64 (128B rows, flash-style swizzle ch^(row&7)),
// 3-stage cp.async pipeline (96 KB -> 2 CTAs/SM), 16 K-stages.
// Epilogue: Ch!=null -> bf16 hi/lo split; else fp32 C.
// ---------------------------------------------------------------------------
#define BKH 64
#define NSTAGE_H (GK / BKH)   // 16
#define STGH 32768            // A 16KB + B 16KB per stage
#define NPIPE 3

__global__ __launch_bounds__(256, 2)
void gemm_f16_kernel(const __half* __restrict__ A,
                     const __half* __restrict__ B,
                     const float* __restrict__ bias,
                     float* __restrict__ C,
                     __nv_bfloat16* __restrict__ Ch,
                     __nv_bfloat16* __restrict__ Cl, int N)
{
    extern __shared__ char smc[];
    const uint32_t sbase = smem_u32(smc);
    const int tid  = threadIdx.x;
    const int wid  = tid >> 5;
    const int lane = tid & 31;
    const int bn = blockIdx.x, bm = blockIdx.y;
    const int wm = wid >> 1;   // 0..3 -> m offset wm*32
    const int wn = wid & 1;    // 0..1 -> n offset wn*64

    const __half* gA = A + (size_t)bm * 128 * GK;
    const __half* gB = B + (size_t)bn * 128 * GK;

    auto stage_load = [&](int c) {
        const int s  = c % NPIPE;
        const int k0 = c * BKH;
#pragma unroll
        for (int t = 0; t < 2; t++) {
            const __half* g = t ? gB : gA;
            const uint32_t sb = sbase + s * STGH + t * 16384;
#pragma unroll
            for (int r2 = 0; r2 < 4; r2++) {
                int idx = tid + r2 * 256;       // 0..1023
                int row = idx >> 3;
                int ch  = idx & 7;
                int sw  = ch ^ (row & 7);
                const __half* src = g + (size_t)row * GK + k0 + ch * 8;
                CP_ASYNC16(sb + row * 128 + sw * 16, src);
            }
        }
        CP_COMMIT();
    };

    float acc[2][8][4];
#pragma unroll
    for (int i = 0; i < 2; i++)
#pragma unroll
        for (int j = 0; j < 8; j++)
#pragma unroll
            for (int q = 0; q < 4; q++) acc[i][j][q] = 0.f;

    // prologue: stages 0,1 in flight; wait for stage 0
    stage_load(0);
    stage_load(1);
    CP_WAIT(1);
    __syncthreads();

    for (int c = 0; c < NSTAGE_H; c++) {
        if (c + 2 < NSTAGE_H) stage_load(c + 2);

        const uint32_t st = sbase + (uint32_t)(c % NPIPE) * STGH;
        const uint32_t sA = st;
        const uint32_t sB = st + 16384;

#pragma unroll
        for (int kk = 0; kk < 4; kk++) {   // four k16 slices of BKH=64
            uint32_t a[2][4];
#pragma unroll
            for (int mf = 0; mf < 2; mf++) {
                int row = wm * 32 + mf * 16 + (lane & 7) + ((lane >> 3) & 1) * 8;
                int ch  = 2 * kk + (lane >> 4);
                uint32_t addr = sA + row * 128 + ((ch ^ (row & 7)) << 4);
                LDMATRIX_X4(a[mf][0], a[mf][1], a[mf][2], a[mf][3], addr);
            }
            uint32_t b[4][4];
#pragma unroll
            for (int p = 0; p < 4; p++) {
                int row = wn * 64 + p * 16 + (lane & 7) + (lane >> 4) * 8;
                int ch  = 2 * kk + ((lane >> 3) & 1);
                uint32_t addr = sB + row * 128 + ((ch ^ (row & 7)) << 4);
                LDMATRIX_X4(b[p][0], b[p][1], b[p][2], b[p][3], addr);
            }
#pragma unroll
            for (int mf = 0; mf < 2; mf++)
#pragma unroll
                for (int p = 0; p < 4; p++)
#pragma unroll
                    for (int h = 0; h < 2; h++) {
                        float* cc = acc[mf][p * 2 + h];
                        MMA16816H(cc[0], cc[1], cc[2], cc[3],
                                  a[mf][0], a[mf][1], a[mf][2], a[mf][3],
                                  b[p][h * 2], b[p][h * 2 + 1]);
                    }
        }

        if (c + 2 < NSTAGE_H)      CP_WAIT(1);
        else if (c + 1 < NSTAGE_H) CP_WAIT(0);
        __syncthreads();
    }

    const int g = lane >> 2, t2 = (lane & 3) * 2;
#pragma unroll
    for (int mf = 0; mf < 2; mf++) {
        int row0 = bm * 128 + wm * 32 + mf * 16 + g;
#pragma unroll
        for (int nf = 0; nf < 8; nf++) {
            int col = bn * 128 + wn * 64 + nf * 8 + t2;
            float bx = bias[col], by = bias[col + 1];
            float v0 = acc[mf][nf][0] + bx, v1 = acc[mf][nf][1] + by;
            float v2 = acc[mf][nf][2] + bx, v3 = acc[mf][nf][3] + by;
            if (Ch) {
                __nv_bfloat162 h01 = __floats2bfloat162_rn(v0, v1);
                __nv_bfloat162 h23 = __floats2bfloat162_rn(v2, v3);
                __nv_bfloat162 l01 = __floats2bfloat162_rn(
                    v0 - __bfloat162float(h01.x), v1 - __bfloat162float(h01.y));
                __nv_bfloat162 l23 = __floats2bfloat162_rn(
                    v2 - __bfloat162float(h23.x), v3 - __bfloat162float(h23.y));
                *(__nv_bfloat162*)(Ch + (size_t)row0 * N + col)       = h01;
                *(__nv_bfloat162*)(Cl + (size_t)row0 * N + col)       = l01;
                *(__nv_bfloat162*)(Ch + (size_t)(row0 + 8) * N + col) = h23;
                *(__nv_bfloat162*)(Cl + (size_t)(row0 + 8) * N + col) = l23;
            } else {
                float2 f0; f0.x = v0; f0.y = v1;
                float2 f1; f1.x = v2; f1.y = v3;
                *(float2*)(C + (size_t)row0 * N + col)       = f0;
                *(float2*)(C + (size_t)(row0 + 8) * N + col) = f1;
            }
        }
    }
}

// ---------------------------------------------------------------------------
// Tensor-core flash attention (bf16 hi/lo compensated, causal). Unchanged core
// from R14 (best); epilogue writes fp16 attn for the proj GEMM.
// ---------------------------------------------------------------------------
__global__ __launch_bounds__(256, 2)
void flash_mma_kernel(const __nv_bfloat16* __restrict__ qkvh,
                      const __nv_bfloat16* __restrict__ qkvl,
                      __half* __restrict__ attn)
{
    extern __shared__ char smf[];
    const uint32_t sb = smem_u32(smf);
    const int tid = threadIdx.x, wid = tid >> 5, lane = tid & 31;
    const int qt = (int)gridDim.x - 1 - (int)blockIdx.x;  // heavy tiles first
    const int h = blockIdx.y, b = blockIdx.z;
    const int g = lane >> 2, t = lane & 3;

    const size_t rowbase = (size_t)b * S_LEN * QKV_N + (size_t)h * HD;

    for (int i = tid; i < 2048; i += 256) {
        int arr = i >> 10;
        int r   = (i >> 3) & 127;
        int ch  = i & 7;
        const __nv_bfloat16* src =
            (arr ? qkvl : qkvh) + rowbase + (size_t)(qt * 128 + r) * QKV_N + ch * 8;
        CP_ASYNC16(sb + arr * 16384 + r * 128 + ((ch ^ (r & 7)) << 4), src);
    }

    auto stage_kv = [&](int kt) {
        const int s = kt & 1;
        for (int i = tid; i < 2048; i += 256) {
            int sub = i >> 9;            // 0 Kh, 1 Kl, 2 Vh, 3 Vl
            int r   = (i >> 3) & 63;
            int ch  = i & 7;
            size_t go = rowbase + (size_t)(kt * 64 + r) * QKV_N + ch * 8
                      + ((sub >> 1) ? 2 * (size_t)EMB : (size_t)EMB);
            const __nv_bfloat16* gp = (sub & 1) ? qkvl + go : qkvh + go;
            CP_ASYNC16(sb + 32768 + s * 32768 + sub * 8192 + r * 128
                       + ((ch ^ (r & 7)) << 4), gp);
        }
        CP_COMMIT();
    };

    stage_kv(0);

    float m_[2] = { -1e30f, -1e30f }, l_[2] = { 0.f, 0.f };
    float oacc[8][4];
#pragma unroll
    for (int i = 0; i < 8; i++)
#pragma unroll
        for (int j = 0; j < 4; j++) oacc[i][j] = 0.f;

    const int nkt  = 2 * qt + 2;
    const int wrow = qt * 128 + wid * 16;

    for (int kt = 0; kt < nkt; kt++) {
        if (kt + 1 < nkt) { stage_kv(kt + 1); CP_WAIT(1); }
        else              { CP_WAIT(0); }
        __syncthreads();

        const bool active = (kt * 64) <= (wrow + 15);
        if (active) {
            const uint32_t stK = sb + 32768 + (uint32_t)(kt & 1) * 32768;
            const uint32_t stV = stK + 16384;

            float sacc[8][4];
#pragma unroll
            for (int i = 0; i < 8; i++)
#pragma unroll
                for (int j = 0; j < 4; j++) sacc[i][j] = 0.f;

#pragma unroll
            for (int kk = 0; kk < 4; kk++) {
                uint32_t aH[4], aL[4];
                {
                    int row = wid * 16 + (lane & 7) + ((lane >> 3) & 1) * 8;
                    int ch  = 2 * kk + (lane >> 4);
                    uint32_t ad = sb + row * 128 + ((ch ^ (row & 7)) << 4);
                    LDMATRIX_X4(aH[0], aH[1], aH[2], aH[3], ad);
                    LDMATRIX_X4(aL[0], aL[1], aL[2], aL[3], ad + 16384);
                }
#pragma unroll
                for (int p = 0; p < 4; p++) {
                    uint32_t bH[4], bL[4];
                    int row = p * 16 + (lane & 7) + (lane >> 4) * 8;
                    int ch  = 2 * kk + ((lane >> 3) & 1);
                    uint32_t bd = stK + row * 128 + ((ch ^ (row & 7)) << 4);
                    LDMATRIX_X4(bH[0], bH[1], bH[2], bH[3], bd);
                    LDMATRIX_X4(bL[0], bL[1], bL[2], bL[3], bd + 8192);
#pragma unroll
                    for (int term = 0; term < 3; term++) {
                        const uint32_t* aa = (term == 2) ? aL : aH;
                        const uint32_t* bb = (term == 1) ? bL : bH;
#pragma unroll
                        for (int hh = 0; hh < 2; hh++) {
                            float* cc = sacc[2 * p + hh];
                            MMA16816(cc[0], cc[1], cc[2], cc[3],
                                     aa[0], aa[1], aa[2], aa[3],
                                     bb[2 * hh], bb[2 * hh + 1]);
                        }
                    }
                }
            }

            const int r0g = wrow + g;
#pragma unroll
            for (int nf = 0; nf < 8; nf++) {
                int c0 = kt * 64 + nf * 8 + 2 * t;
#pragma unroll
                for (int e = 0; e < 2; e++) {
                    int col = c0 + e;
                    sacc[nf][e]     = (col <= r0g)     ? sacc[nf][e] * 0.125f     : -1e30f;
                    sacc[nf][2 + e] = (col <= r0g + 8) ? sacc[nf][2 + e] * 0.125f : -1e30f;
                }
            }

#pragma unroll
            for (int hf = 0; hf < 2; hf++) {
                float mx = -1e30f;
#pragma unroll
                for (int nf = 0; nf < 8; nf++)
                    mx = fmaxf(mx, fmaxf(sacc[nf][2 * hf], sacc[nf][2 * hf + 1]));
                mx = fmaxf(mx, __shfl_xor_sync(0xffffffffu, mx, 1));
                mx = fmaxf(mx, __shfl_xor_sync(0xffffffffu, mx, 2));
                float mnew  = fmaxf(m_[hf], mx);
                float alpha = __expf(m_[hf] - mnew);
                float rsum = 0.f;
#pragma unroll
                for (int nf = 0; nf < 8; nf++) {
                    float e0 = __expf(sacc[nf][2 * hf] - mnew);
                    float e1 = __expf(sacc[nf][2 * hf + 1] - mnew);
                    sacc[nf][2 * hf] = e0; sacc[nf][2 * hf + 1] = e1;
                    rsum += e0 + e1;
                }
                rsum += __shfl_xor_sync(0xffffffffu, rsum, 1);
                rsum += __shfl_xor_sync(0xffffffffu, rsum, 2);
                l_[hf] = l_[hf] * alpha + rsum;
                m_[hf] = mnew;
#pragma unroll
                for (int nf = 0; nf < 8; nf++) {
                    oacc[nf][2 * hf]     *= alpha;
                    oacc[nf][2 * hf + 1] *= alpha;
                }
            }

#pragma unroll
            for (int s16 = 0; s16 < 4; s16++) {
                uint32_t pH[4], pL[4];
                {
                    const int nfl = 2 * s16, nfh = 2 * s16 + 1;
                    __nv_bfloat162 h0 = __floats2bfloat162_rn(sacc[nfl][0], sacc[nfl][1]);
                    __nv_bfloat162 h1 = __floats2bfloat162_rn(sacc[nfl][2], sacc[nfl][3]);
                    __nv_bfloat162 h2 = __floats2bfloat162_rn(sacc[nfh][0], sacc[nfh][1]);
                    __nv_bfloat162 h3 = __floats2bfloat162_rn(sacc[nfh][2], sacc[nfh][3]);
                    pH[0] = bf2u(h0); pH[1] = bf2u(h1); pH[2] = bf2u(h2); pH[3] = bf2u(h3);
                    __nv_bfloat162 e0 = __floats2bfloat162_rn(
                        sacc[nfl][0] - __bfloat162float(h0.x), sacc[nfl][1] - __bfloat162float(h0.y));
                    __nv_bfloat162 e1 = __floats2bfloat162_rn(
                        sacc[nfl][2] - __bfloat162float(h1.x), sacc[nfl][3] - __bfloat162float(h1.y));
                    __nv_bfloat162 e2 = __floats2bfloat162_rn(
                        sacc[nfh][0] - __bfloat162float(h2.x), sacc[nfh][1] - __bfloat162float(h2.y));
                    __nv_bfloat162 e3 = __floats2bfloat162_rn(
                        sacc[nfh][2] - __bfloat162float(h3.x), sacc[nfh][3] - __bfloat162float(h3.y));
                    pL[0] = bf2u(e0); pL[1] = bf2u(e1); pL[2] = bf2u(e2); pL[3] = bf2u(e3);
                }
#pragma unroll
                for (int p = 0; p < 4; p++) {
                    uint32_t vH[4], vL[4];
                    int row = s16 * 16 + (lane & 7) + ((lane >> 3) & 1) * 8;
                    int ch  = 2 * p + (lane >> 4);
                    uint32_t vd = stV + row * 128 + ((ch ^ (row & 7)) << 4);
                    LDMATRIX_X4_T(vH[0], vH[1], vH[2], vH[3], vd);
                    LDMATRIX_X4_T(vL[0], vL[1], vL[2], vL[3], vd + 8192);
#pragma unroll
                    for (int term = 0; term < 3; term++) {
                        const uint32_t* pp = (term == 2) ? pL : pH;
                        const uint32_t* vv = (term == 1) ? vL : vH;
#pragma unroll
                        for (int hh = 0; hh < 2; hh++) {
                            float* cc = oacc[2 * p + hh];
                            MMA16816(cc[0], cc[1], cc[2], cc[3],
                                     pp[0], pp[1], pp[2], pp[3],
                                     vv[2 * hh], vv[2 * hh + 1]);
                        }
                    }
                }
            }
        }
        __syncthreads();
    }

    // epilogue: O / l -> fp16 (feeds proj GEMM)
    const float inv0 = 1.f / l_[0], inv1 = 1.f / l_[1];
    const int grow0 = qt * 128 + wid * 16 + g;
    const size_t obase = (size_t)b * S_LEN * EMB + (size_t)h * HD;
#pragma unroll
    for (int nf = 0; nf < 8; nf++) {
        int d = nf * 8 + 2 * t;
        __half2 f0 = __floats2half2_rn(oacc[nf][0] * inv0, oacc[nf][1] * inv0);
        __half2 f1 = __floats2half2_rn(oacc[nf][2] * inv1, oacc[nf][3] * inv1);
        *(__half2*)(attn + obase + (size_t)grow0 * EMB + d)       = f0;
        *(__half2*)(attn + obase + (size_t)(grow0 + 8) * EMB + d) = f1;
    }
}

// ---------------------------------------------------------------------------
// launch
// ---------------------------------------------------------------------------
extern "C" void kernel_launch(void* const* d_in, const int* in_sizes, int n_in,
                              void* d_out, int out_size)
{
    const float* x     = (const float*)d_in[0];
    const float* wqkv  = (const float*)d_in[1];
    const float* bqkv  = (const float*)d_in[2];
    const float* wproj = (const float*)d_in[3];
    const float* bproj = (const float*)d_in[4];
    float* out = (float*)d_out;

    __nv_bfloat16 *qkvh, *qkvl;
    __half *x16, *at16, *wq16, *wp16;
    cudaGetSymbolAddress((void**)&qkvh, g_qkvh);
    cudaGetSymbolAddress((void**)&qkvl, g_qkvl);
    cudaGetSymbolAddress((void**)&x16,  g_x16);
    cudaGetSymbolAddress((void**)&at16, g_at16);
    cudaGetSymbolAddress((void**)&wq16, g_wq16);
    cudaGetSymbolAddress((void**)&wp16, g_wp16);

    const int gemm_smem  = NPIPE * STGH;            // 96 KB -> 2 CTAs/SM
    const int flash_smem = 32768 + 2 * 32768;       // 96 KB
    cudaFuncSetAttribute(gemm_f16_kernel,
                         cudaFuncAttributeMaxDynamicSharedMemorySize, gemm_smem);
    cudaFuncSetAttribute(flash_mma_kernel,
                         cudaFuncAttributeMaxDynamicSharedMemorySize, flash_smem);

    // 0) converts: X -> fp16 ; Wqkv -> [3E,E] fp16 ; Wproj -> [E,E] fp16
    {
        int n4 = ROWS * EMB / 4;
        conv16_kernel<<<(n4 + 255) / 256, 256>>>(x, x16, n4);
        dim3 wb(32, 8);
        wconv_kernel<<<dim3(QKV_N / 32, EMB / 32), wb>>>(wqkv, wq16, EMB, QKV_N);
        wconv_kernel<<<dim3(EMB / 32, EMB / 32), wb>>>(wproj, wp16, EMB, EMB);
    }

    // 1) QKV = X @ Wqkv + b (fp16 single-pass) -> bf16 hi/lo for flash
    {
        dim3 grid(QKV_N / 128, ROWS / 128);
        gemm_f16_kernel<<<grid, 256, gemm_smem>>>(x16, wq16, bqkv,
                                                  nullptr, qkvh, qkvl, QKV_N);
    }

    // 2) tensor-core causal flash attention (bf16x3) -> fp16 attn
    {
        dim3 grid(S_LEN / 128, NH, BATCH);
        flash_mma_kernel<<<grid, 256, flash_smem>>>(qkvh, qkvl, at16);
    }

    // 3) out = attn @ Wproj + b (fp16 single-pass, fp32 out)
    {
        dim3 grid(EMB / 128, ROWS / 128);
        gemm_f16_kernel<<<grid, 256, gemm_smem>>>(at16, wp16, bproj,
                                                  out, nullptr, nullptr, EMB);
    }
}

// round 17
// speedup vs baseline: 3.7727x; 1.2026x over previous
#include <cuda_runtime.h>
#include <cuda_bf16.h>
#include <cuda_fp16.h>
#include <cstdint>

// Problem constants
#define BATCH 2
#define S_LEN 2048
#define EMB   1024
#define NH    16
#define HD    64
#define QKV_N (3 * EMB)        // 3072
#define ROWS  (BATCH * S_LEN)  // 4096
#define GK    EMB              // GEMM K = 1024 for both GEMMs

// ---------------------------------------------------------------------------
// Scratch (device globals — allocation-free)
// g_qkvh: Q,K cols = bf16 hi; V cols (>=2048) = fp16 full (single-pass PV)
// g_qkvl: Q,K cols = bf16 lo; V cols unused
// ---------------------------------------------------------------------------
__device__ __align__(256) __nv_bfloat16 g_qkvh[ (size_t)ROWS * QKV_N ];
__device__ __align__(256) __nv_bfloat16 g_qkvl[ (size_t)ROWS * QKV_N ];
__device__ __align__(256) __half g_x16 [ (size_t)ROWS * EMB ];          // X fp16
__device__ __align__(256) __half g_at16[ (size_t)ROWS * EMB ];          // attn fp16
__device__ __align__(256) __half g_wq16[ (size_t)QKV_N * EMB ];         // Wqkv^T [N,K]
__device__ __align__(256) __half g_wp16[ (size_t)EMB * EMB ];           // Wproj^T [N,K]

// ---------------------------------------------------------------------------
// helpers (non-arch-gated PTX only: cp.async / ldmatrix / mma.sync)
// ---------------------------------------------------------------------------
__device__ __forceinline__ uint32_t smem_u32(const void* p) {
    uint32_t a;
    asm("{ .reg .u64 t; cvta.to.shared.u64 t, %1; cvt.u32.u64 %0, t; }"
        : "=r"(a) : "l"(p));
    return a;
}

#define CP_ASYNC16(dst, src) \
    asm volatile("cp.async.cg.shared.global [%0], [%1], 16;" :: "r"(dst), "l"(src))
#define CP_COMMIT() asm volatile("cp.async.commit_group;" ::: "memory")
#define CP_WAIT(n)  asm volatile("cp.async.wait_group %0;" :: "n"(n) : "memory")

#define LDMATRIX_X4(r0, r1, r2, r3, addr) \
    asm volatile("ldmatrix.sync.aligned.m8n8.x4.shared.b16 {%0,%1,%2,%3}, [%4];" \
                 : "=r"(r0), "=r"(r1), "=r"(r2), "=r"(r3) : "r"(addr))

#define LDMATRIX_X4_T(r0, r1, r2, r3, addr) \
    asm volatile("ldmatrix.sync.aligned.m8n8.x4.trans.shared.b16 {%0,%1,%2,%3}, [%4];" \
                 : "=r"(r0), "=r"(r1), "=r"(r2), "=r"(r3) : "r"(addr))

// bf16 MMA (flash QK)
#define MMA16816(c0, c1, c2, c3, a0, a1, a2, a3, b0, b1)                        \
    asm volatile("mma.sync.aligned.m16n8k16.row.col.f32.bf16.bf16.f32 "         \
                 "{%0,%1,%2,%3}, {%4,%5,%6,%7}, {%8,%9}, {%0,%1,%2,%3};"        \
                 : "+f"(c0), "+f"(c1), "+f"(c2), "+f"(c3)                       \
                 : "r"(a0), "r"(a1), "r"(a2), "r"(a3), "r"(b0), "r"(b1))

// fp16 MMA (GEMMs + flash PV)
#define MMA16816H(c0, c1, c2, c3, a0, a1, a2, a3, b0, b1)                       \
    asm volatile("mma.sync.aligned.m16n8k16.row.col.f32.f16.f16.f32 "           \
                 "{%0,%1,%2,%3}, {%4,%5,%6,%7}, {%8,%9}, {%0,%1,%2,%3};"        \
                 : "+f"(c0), "+f"(c1), "+f"(c2), "+f"(c3)                       \
                 : "r"(a0), "r"(a1), "r"(a2), "r"(a3), "r"(b0), "r"(b1))

__device__ __forceinline__ uint32_t bf2u(__nv_bfloat162 v) {
    return *reinterpret_cast<uint32_t*>(&v);
}
__device__ __forceinline__ uint32_t h2u(__half2 v) {
    return *reinterpret_cast<uint32_t*>(&v);
}

// ---------------------------------------------------------------------------
// fp32 -> fp16 convert (float4 vectorized)
// ---------------------------------------------------------------------------
__global__ void conv16_kernel(const float* __restrict__ in,
                              __half* __restrict__ out, int n4)
{
    int i = blockIdx.x * blockDim.x + threadIdx.x;
    if (i >= n4) return;
    float4 v = ((const float4*)in)[i];
    ((__half2*)out)[2 * i]     = __floats2half2_rn(v.x, v.y);
    ((__half2*)out)[2 * i + 1] = __floats2half2_rn(v.z, v.w);
}

// ---------------------------------------------------------------------------
// Weight transpose + convert: W[K,N] fp32 -> T[N,K] fp16
// ---------------------------------------------------------------------------
__global__ void wconv_kernel(const float* __restrict__ W,
                             __half* __restrict__ T, int K, int N)
{
    __shared__ float t[32][33];
    int tx = threadIdx.x, ty = threadIdx.y;
    int n0 = blockIdx.x * 32, k0 = blockIdx.y * 32;
    for (int j = ty; j < 32; j += 8)
        t[j][tx] = W[(size_t)(k0 + j) * N + n0 + tx];
    __syncthreads();
    for (int j = ty; j < 32; j += 8)
        T[(size_t)(n0 + j) * K + k0 + tx] = __float2half_rn(t[tx][j]);
}

// ---------------------------------------------------------------------------
// fp16 single-pass GEMM via mma.sync m16n8k16.f16: C = A@Bt^T + bias.
// CTA 128x128, BKH=64 (128B rows, swizzle ch^(row&7)), 3-stage pipeline,
// 96 KB smem -> 2 CTAs/SM.
// Epilogue modes: Ch==null -> fp32 C; Ch!=null & col<vcol -> bf16 hi/lo;
//                 Ch!=null & col>=vcol -> fp16 full (V region for flash PV).
// ---------------------------------------------------------------------------
#define BKH 64
#define NSTAGE_H (GK / BKH)   // 16
#define STGH 32768            // A 16KB + B 16KB per stage
#define NPIPE 3

__global__ __launch_bounds__(256, 2)
void gemm_f16_kernel(const __half* __restrict__ A,
                     const __half* __restrict__ B,
                     const float* __restrict__ bias,
                     float* __restrict__ C,
                     __nv_bfloat16* __restrict__ Ch,
                     __nv_bfloat16* __restrict__ Cl, int N, int vcol)
{
    extern __shared__ char smc[];
    const uint32_t sbase = smem_u32(smc);
    const int tid  = threadIdx.x;
    const int wid  = tid >> 5;
    const int lane = tid & 31;
    const int bn = blockIdx.x, bm = blockIdx.y;
    const int wm = wid >> 1;   // 0..3 -> m offset wm*32
    const int wn = wid & 1;    // 0..1 -> n offset wn*64
    const bool vmode = (bn * 128) >= vcol;

    const __half* gA = A + (size_t)bm * 128 * GK;
    const __half* gB = B + (size_t)bn * 128 * GK;

    auto stage_load = [&](int c) {
        const int s  = c % NPIPE;
        const int k0 = c * BKH;
#pragma unroll
        for (int t = 0; t < 2; t++) {
            const __half* g = t ? gB : gA;
            const uint32_t sb = sbase + s * STGH + t * 16384;
#pragma unroll
            for (int r2 = 0; r2 < 4; r2++) {
                int idx = tid + r2 * 256;       // 0..1023
                int row = idx >> 3;
                int ch  = idx & 7;
                int sw  = ch ^ (row & 7);
                const __half* src = g + (size_t)row * GK + k0 + ch * 8;
                CP_ASYNC16(sb + row * 128 + sw * 16, src);
            }
        }
        CP_COMMIT();
    };

    float acc[2][8][4];
#pragma unroll
    for (int i = 0; i < 2; i++)
#pragma unroll
        for (int j = 0; j < 8; j++)
#pragma unroll
            for (int q = 0; q < 4; q++) acc[i][j][q] = 0.f;

    stage_load(0);
    stage_load(1);
    CP_WAIT(1);
    __syncthreads();

    for (int c = 0; c < NSTAGE_H; c++) {
        if (c + 2 < NSTAGE_H) stage_load(c + 2);

        const uint32_t st = sbase + (uint32_t)(c % NPIPE) * STGH;
        const uint32_t sA = st;
        const uint32_t sB = st + 16384;

#pragma unroll
        for (int kk = 0; kk < 4; kk++) {   // four k16 slices of BKH=64
            uint32_t a[2][4];
#pragma unroll
            for (int mf = 0; mf < 2; mf++) {
                int row = wm * 32 + mf * 16 + (lane & 7) + ((lane >> 3) & 1) * 8;
                int ch  = 2 * kk + (lane >> 4);
                uint32_t addr = sA + row * 128 + ((ch ^ (row & 7)) << 4);
                LDMATRIX_X4(a[mf][0], a[mf][1], a[mf][2], a[mf][3], addr);
            }
            uint32_t b[4][4];
#pragma unroll
            for (int p = 0; p < 4; p++) {
                int row = wn * 64 + p * 16 + (lane & 7) + (lane >> 4) * 8;
                int ch  = 2 * kk + ((lane >> 3) & 1);
                uint32_t addr = sB + row * 128 + ((ch ^ (row & 7)) << 4);
                LDMATRIX_X4(b[p][0], b[p][1], b[p][2], b[p][3], addr);
            }
#pragma unroll
            for (int mf = 0; mf < 2; mf++)
#pragma unroll
                for (int p = 0; p < 4; p++)
#pragma unroll
                    for (int h = 0; h < 2; h++) {
                        float* cc = acc[mf][p * 2 + h];
                        MMA16816H(cc[0], cc[1], cc[2], cc[3],
                                  a[mf][0], a[mf][1], a[mf][2], a[mf][3],
                                  b[p][h * 2], b[p][h * 2 + 1]);
                    }
        }

        if (c + 2 < NSTAGE_H)      CP_WAIT(1);
        else if (c + 1 < NSTAGE_H) CP_WAIT(0);
        __syncthreads();
    }

    const int g = lane >> 2, t2 = (lane & 3) * 2;
#pragma unroll
    for (int mf = 0; mf < 2; mf++) {
        int row0 = bm * 128 + wm * 32 + mf * 16 + g;
#pragma unroll
        for (int nf = 0; nf < 8; nf++) {
            int col = bn * 128 + wn * 64 + nf * 8 + t2;
            float bx = bias[col], by = bias[col + 1];
            float v0 = acc[mf][nf][0] + bx, v1 = acc[mf][nf][1] + by;
            float v2 = acc[mf][nf][2] + bx, v3 = acc[mf][nf][3] + by;
            if (Ch) {
                if (vmode) {
                    // V region: full fp16 (single-pass PV consumes this)
                    *(__half2*)(Ch + (size_t)row0 * N + col) =
                        __floats2half2_rn(v0, v1);
                    *(__half2*)(Ch + (size_t)(row0 + 8) * N + col) =
                        __floats2half2_rn(v2, v3);
                } else {
                    __nv_bfloat162 h01 = __floats2bfloat162_rn(v0, v1);
                    __nv_bfloat162 h23 = __floats2bfloat162_rn(v2, v3);
                    __nv_bfloat162 l01 = __floats2bfloat162_rn(
                        v0 - __bfloat162float(h01.x), v1 - __bfloat162float(h01.y));
                    __nv_bfloat162 l23 = __floats2bfloat162_rn(
                        v2 - __bfloat162float(h23.x), v3 - __bfloat162float(h23.y));
                    *(__nv_bfloat162*)(Ch + (size_t)row0 * N + col)       = h01;
                    *(__nv_bfloat162*)(Cl + (size_t)row0 * N + col)       = l01;
                    *(__nv_bfloat162*)(Ch + (size_t)(row0 + 8) * N + col) = h23;
                    *(__nv_bfloat162*)(Cl + (size_t)(row0 + 8) * N + col) = l23;
                }
            } else {
                float2 f0; f0.x = v0; f0.y = v1;
                float2 f1; f1.x = v2; f1.y = v3;
                *(float2*)(C + (size_t)row0 * N + col)       = f0;
                *(float2*)(C + (size_t)(row0 + 8) * N + col) = f1;
            }
        }
    }
}

// ---------------------------------------------------------------------------
// Tensor-core flash attention, causal. QK = bf16 hi/lo 3-term; PV = fp16 1-term.
// BM=128 (8 warps x m16), BN=64, D=64. grid = (S/128, NH, B), 256 threads.
// smem: Qh(16K) Ql(16K) | 2 stages x [Kh(8K) Kl(8K) V16(8K)] = 80 KB.
// Swizzle on 128B rows: chunk' = ch ^ (row & 7).
// ---------------------------------------------------------------------------
#define FSTG 24576

__global__ __launch_bounds__(256, 2)
void flash_mma_kernel(const __nv_bfloat16* __restrict__ qkvh,
                      const __nv_bfloat16* __restrict__ qkvl,
                      __half* __restrict__ attn)
{
    extern __shared__ char smf[];
    const uint32_t sb = smem_u32(smf);
    const int tid = threadIdx.x, wid = tid >> 5, lane = tid & 31;
    const int qt = (int)gridDim.x - 1 - (int)blockIdx.x;  // heavy tiles first
    const int h = blockIdx.y, b = blockIdx.z;
    const int g = lane >> 2, t = lane & 3;

    const size_t rowbase = (size_t)b * S_LEN * QKV_N + (size_t)h * HD;

    // ---- Q tile (hi+lo): 128 rows x 8 chunks x 2
    for (int i = tid; i < 2048; i += 256) {
        int arr = i >> 10;
        int r   = (i >> 3) & 127;
        int ch  = i & 7;
        const __nv_bfloat16* src =
            (arr ? qkvl : qkvh) + rowbase + (size_t)(qt * 128 + r) * QKV_N + ch * 8;
        CP_ASYNC16(sb + arr * 16384 + r * 128 + ((ch ^ (r & 7)) << 4), src);
    }

    auto stage_kv = [&](int kt) {
        const int s = kt & 1;
        for (int i = tid; i < 1536; i += 256) {
            int sub = i >> 9;            // 0 Kh, 1 Kl, 2 V(fp16 in qkvh)
            int r   = (i >> 3) & 63;
            int ch  = i & 7;
            size_t go = rowbase + (size_t)(kt * 64 + r) * QKV_N + ch * 8
                      + ((sub == 2) ? 2 * (size_t)EMB : (size_t)EMB);
            const __nv_bfloat16* gp = (sub == 1) ? qkvl + go : qkvh + go;
            CP_ASYNC16(sb + 32768 + s * FSTG + sub * 8192 + r * 128
                       + ((ch ^ (r & 7)) << 4), gp);
        }
        CP_COMMIT();
    };

    stage_kv(0);   // commits Q + stage0 together (group 0)

    float m_[2] = { -1e30f, -1e30f }, l_[2] = { 0.f, 0.f };
    float oacc[8][4];
#pragma unroll
    for (int i = 0; i < 8; i++)
#pragma unroll
        for (int j = 0; j < 4; j++) oacc[i][j] = 0.f;

    const int nkt  = 2 * qt + 2;
    const int wrow = qt * 128 + wid * 16;

    for (int kt = 0; kt < nkt; kt++) {
        if (kt + 1 < nkt) { stage_kv(kt + 1); CP_WAIT(1); }
        else              { CP_WAIT(0); }
        __syncthreads();

        const bool active = (kt * 64) <= (wrow + 15);
        if (active) {
            const uint32_t stK = sb + 32768 + (uint32_t)(kt & 1) * FSTG;
            const uint32_t stV = stK + 16384;

            // ---- S = Q K^T (bf16 3-term compensated)
            float sacc[8][4];
#pragma unroll
            for (int i = 0; i < 8; i++)
#pragma unroll
                for (int j = 0; j < 4; j++) sacc[i][j] = 0.f;

#pragma unroll
            for (int kk = 0; kk < 4; kk++) {
                uint32_t aH[4], aL[4];
                {
                    int row = wid * 16 + (lane & 7) + ((lane >> 3) & 1) * 8;
                    int ch  = 2 * kk + (lane >> 4);
                    uint32_t ad = sb + row * 128 + ((ch ^ (row & 7)) << 4);
                    LDMATRIX_X4(aH[0], aH[1], aH[2], aH[3], ad);
                    LDMATRIX_X4(aL[0], aL[1], aL[2], aL[3], ad + 16384);
                }
#pragma unroll
                for (int p = 0; p < 4; p++) {
                    uint32_t bH[4], bL[4];
                    int row = p * 16 + (lane & 7) + (lane >> 4) * 8;
                    int ch  = 2 * kk + ((lane >> 3) & 1);
                    uint32_t bd = stK + row * 128 + ((ch ^ (row & 7)) << 4);
                    LDMATRIX_X4(bH[0], bH[1], bH[2], bH[3], bd);
                    LDMATRIX_X4(bL[0], bL[1], bL[2], bL[3], bd + 8192);
#pragma unroll
                    for (int term = 0; term < 3; term++) {
                        const uint32_t* aa = (term == 2) ? aL : aH;
                        const uint32_t* bb = (term == 1) ? bL : bH;
#pragma unroll
                        for (int hh = 0; hh < 2; hh++) {
                            float* cc = sacc[2 * p + hh];
                            MMA16816(cc[0], cc[1], cc[2], cc[3],
                                     aa[0], aa[1], aa[2], aa[3],
                                     bb[2 * hh], bb[2 * hh + 1]);
                        }
                    }
                }
            }

            // ---- scale + causal mask
            const int r0g = wrow + g;
#pragma unroll
            for (int nf = 0; nf < 8; nf++) {
                int c0 = kt * 64 + nf * 8 + 2 * t;
#pragma unroll
                for (int e = 0; e < 2; e++) {
                    int col = c0 + e;
                    sacc[nf][e]     = (col <= r0g)     ? sacc[nf][e] * 0.125f     : -1e30f;
                    sacc[nf][2 + e] = (col <= r0g + 8) ? sacc[nf][2 + e] * 0.125f : -1e30f;
                }
            }

            // ---- online softmax (rows g, g+8 per thread; quad reduction)
#pragma unroll
            for (int hf = 0; hf < 2; hf++) {
                float mx = -1e30f;
#pragma unroll
                for (int nf = 0; nf < 8; nf++)
                    mx = fmaxf(mx, fmaxf(sacc[nf][2 * hf], sacc[nf][2 * hf + 1]));
                mx = fmaxf(mx, __shfl_xor_sync(0xffffffffu, mx, 1));
                mx = fmaxf(mx, __shfl_xor_sync(0xffffffffu, mx, 2));
                float mnew  = fmaxf(m_[hf], mx);
                float alpha = __expf(m_[hf] - mnew);
                float rsum = 0.f;
#pragma unroll
                for (int nf = 0; nf < 8; nf++) {
                    float e0 = __expf(sacc[nf][2 * hf] - mnew);
                    float e1 = __expf(sacc[nf][2 * hf + 1] - mnew);
                    sacc[nf][2 * hf] = e0; sacc[nf][2 * hf + 1] = e1;
                    rsum += e0 + e1;
                }
                rsum += __shfl_xor_sync(0xffffffffu, rsum, 1);
                rsum += __shfl_xor_sync(0xffffffffu, rsum, 2);
                l_[hf] = l_[hf] * alpha + rsum;
                m_[hf] = mnew;
#pragma unroll
                for (int nf = 0; nf < 8; nf++) {
                    oacc[nf][2 * hf]     *= alpha;
                    oacc[nf][2 * hf + 1] *= alpha;
                }
            }

            // ---- O += P V  (fp16 single-term: P->fp16, V fp16 in smem)
#pragma unroll
            for (int s16 = 0; s16 < 4; s16++) {
                uint32_t pH[4];
                {
                    const int nfl = 2 * s16, nfh = 2 * s16 + 1;
                    pH[0] = h2u(__floats2half2_rn(sacc[nfl][0], sacc[nfl][1]));
                    pH[1] = h2u(__floats2half2_rn(sacc[nfl][2], sacc[nfl][3]));
                    pH[2] = h2u(__floats2half2_rn(sacc[nfh][0], sacc[nfh][1]));
                    pH[3] = h2u(__floats2half2_rn(sacc[nfh][2], sacc[nfh][3]));
                }
#pragma unroll
                for (int p = 0; p < 4; p++) {
                    uint32_t vH[4];
                    int row = s16 * 16 + (lane & 7) + ((lane >> 3) & 1) * 8;
                    int ch  = 2 * p + (lane >> 4);
                    uint32_t vd = stV + row * 128 + ((ch ^ (row & 7)) << 4);
                    LDMATRIX_X4_T(vH[0], vH[1], vH[2], vH[3], vd);
#pragma unroll
                    for (int hh = 0; hh < 2; hh++) {
                        float* cc = oacc[2 * p + hh];
                        MMA16816H(cc[0], cc[1], cc[2], cc[3],
                                  pH[0], pH[1], pH[2], pH[3],
                                  vH[2 * hh], vH[2 * hh + 1]);
                    }
                }
            }
        }
        __syncthreads();
    }

    // ---- epilogue: O / l -> fp16 (feeds proj GEMM)
    const float inv0 = 1.f / l_[0], inv1 = 1.f / l_[1];
    const int grow0 = qt * 128 + wid * 16 + g;
    const size_t obase = (size_t)b * S_LEN * EMB + (size_t)h * HD;
#pragma unroll
    for (int nf = 0; nf < 8; nf++) {
        int d = nf * 8 + 2 * t;
        __half2 f0 = __floats2half2_rn(oacc[nf][0] * inv0, oacc[nf][1] * inv0);
        __half2 f1 = __floats2half2_rn(oacc[nf][2] * inv1, oacc[nf][3] * inv1);
        *(__half2*)(attn + obase + (size_t)grow0 * EMB + d)       = f0;
        *(__half2*)(attn + obase + (size_t)(grow0 + 8) * EMB + d) = f1;
    }
}

// ---------------------------------------------------------------------------
// launch
// ---------------------------------------------------------------------------
extern "C" void kernel_launch(void* const* d_in, const int* in_sizes, int n_in,
                              void* d_out, int out_size)
{
    const float* x     = (const float*)d_in[0];
    const float* wqkv  = (const float*)d_in[1];
    const float* bqkv  = (const float*)d_in[2];
    const float* wproj = (const float*)d_in[3];
    const float* bproj = (const float*)d_in[4];
    float* out = (float*)d_out;

    __nv_bfloat16 *qkvh, *qkvl;
    __half *x16, *at16, *wq16, *wp16;
    cudaGetSymbolAddress((void**)&qkvh, g_qkvh);
    cudaGetSymbolAddress((void**)&qkvl, g_qkvl);
    cudaGetSymbolAddress((void**)&x16,  g_x16);
    cudaGetSymbolAddress((void**)&at16, g_at16);
    cudaGetSymbolAddress((void**)&wq16, g_wq16);
    cudaGetSymbolAddress((void**)&wp16, g_wp16);

    const int gemm_smem  = NPIPE * STGH;            // 96 KB -> 2 CTAs/SM
    const int flash_smem = 32768 + 2 * FSTG;        // 80 KB -> 2 CTAs/SM
    cudaFuncSetAttribute(gemm_f16_kernel,
                         cudaFuncAttributeMaxDynamicSharedMemorySize, gemm_smem);
    cudaFuncSetAttribute(flash_mma_kernel,
                         cudaFuncAttributeMaxDynamicSharedMemorySize, flash_smem);

    // 0) converts: X -> fp16 ; Wqkv -> [3E,E] fp16 ; Wproj -> [E,E] fp16
    {
        int n4 = ROWS * EMB / 4;
        conv16_kernel<<<(n4 + 255) / 256, 256>>>(x, x16, n4);
        dim3 wb(32, 8);
        wconv_kernel<<<dim3(QKV_N / 32, EMB / 32), wb>>>(wqkv, wq16, EMB, QKV_N);
        wconv_kernel<<<dim3(EMB / 32, EMB / 32), wb>>>(wproj, wp16, EMB, EMB);
    }

    // 1) QKV = X @ Wqkv + b: Q,K -> bf16 hi/lo; V -> fp16 full (col >= 2048)
    {
        dim3 grid(QKV_N / 128, ROWS / 128);
        gemm_f16_kernel<<<grid, 256, gemm_smem>>>(x16, wq16, bqkv,
                                                  nullptr, qkvh, qkvl,
                                                  QKV_N, 2 * EMB);
    }

    // 2) flash attention (QK bf16x3, PV fp16x1) -> fp16 attn
    {
        dim3 grid(S_LEN / 128, NH, BATCH);
        flash_mma_kernel<<<grid, 256, flash_smem>>>(qkvh, qkvl, at16);
    }

    // 3) out = attn @ Wproj + b (fp16 single-pass, fp32 out)
    {
        dim3 grid(EMB / 128, ROWS / 128);
        gemm_f16_kernel<<<grid, 256, gemm_smem>>>(at16, wp16, bproj,
                                                  out, nullptr, nullptr,
                                                  EMB, 1 << 30);
    }
}